// round 10
// baseline (speedup 1.0000x reference)
#include <cuda_runtime.h>
#include <cuda_bf16.h>

// Problem constants (fixed shapes per reference):
//   z: [32,256,64,64] f32 -> flat [131072, 256]
//   codebook: [512, 256], n_i: [512], e_i: [512,256]
#define NR 131072
#define DD 256
#define KK 512
#define NV4 (NR * DD / 4)

// Output layout (concatenated reference tuple, all float32):
#define OFF_LOSS 33554432
#define OFF_ENC  33554433
#define OFF_CB   33685505
#define OFF_N    33816577
#define OFF_E    33817089

#define NSEG 8
#define PITCH_A 528          // 256 bf16 (512B) + 16B pad: ldmatrix conflict-free
#define PITCH_B 80           // 32 bf16 (64B) + 16B pad
#define SM_A_BYTES (128 * PITCH_A)            // 67584 per split
#define SM_B_SPLIT (128 * PITCH_B)            // 10240
#define SM_B_BUF   (2 * SM_B_SPLIT)           // 20480 per buffer
// dynamic smem layout
#define SMO_AHI  0
#define SMO_ALO  (SM_A_BYTES)
#define SMO_B    (2 * SM_A_BYTES)             // 2 bufs x 2 splits
#define SMO_HN   (2 * SM_A_BYTES + 2 * SM_B_BUF)
#define SM_TOTAL (SMO_HN + KK * 4)            // 178176 B

// -------- device scratch (no allocations allowed) --------
static __device__ int    g_enc[NR];
static __device__ int    g_rowlist[NR];
static __device__ int    g_counts[KK];
static __device__ int    g_offsets[KK];
static __device__ int    g_cursor[KK];
static __device__ float  g_halfnorm[KK];
static __device__ double g_hnd[KK];
static __device__ int    g_fixn;
static __device__ int    g_fixrows[8192];
static __device__ float  g_epart[KK * NSEG * DD];
static __device__ double g_losspart[8192];
static __device__ __nv_bfloat16 g_cbhi[KK * DD];
static __device__ __nv_bfloat16 g_cblo[KK * DD];

// -------- PTX helpers --------
__device__ __forceinline__ unsigned smem_u32(const void* p) {
    unsigned a;
    asm("{ .reg .u64 t; cvta.to.shared.u64 t, %1; cvt.u32.u64 %0, t; }"
        : "=r"(a) : "l"(p));
    return a;
}
__device__ __forceinline__ void cp16(unsigned dst, const void* src) {
    asm volatile("cp.async.cg.shared.global [%0], [%1], 16;"
                 :: "r"(dst), "l"(__cvta_generic_to_global(src)));
}
__device__ __forceinline__ void cp_commit() { asm volatile("cp.async.commit_group;"); }
__device__ __forceinline__ void cp_wait_all() { asm volatile("cp.async.wait_group 0;"); }

__device__ __forceinline__ void ldm_x4(unsigned* r, unsigned addr) {
    asm volatile("ldmatrix.sync.aligned.m8n8.x4.shared.b16 {%0,%1,%2,%3}, [%4];"
                 : "=r"(r[0]), "=r"(r[1]), "=r"(r[2]), "=r"(r[3]) : "r"(addr));
}
__device__ __forceinline__ void mma16816(float* c, const unsigned* a,
                                         unsigned b0, unsigned b1) {
    asm volatile(
        "mma.sync.aligned.m16n8k16.row.col.f32.bf16.bf16.f32 "
        "{%0,%1,%2,%3}, {%4,%5,%6,%7}, {%8,%9}, {%0,%1,%2,%3};"
        : "+f"(c[0]), "+f"(c[1]), "+f"(c[2]), "+f"(c[3])
        : "r"(a[0]), "r"(a[1]), "r"(a[2]), "r"(a[3]), "r"(b0), "r"(b1));
}
__device__ __forceinline__ uint2 bf16x4_hi(float4 v, uint2& lo) {
    __nv_bfloat16 hx = __float2bfloat16(v.x), hy = __float2bfloat16(v.y);
    __nv_bfloat16 hz = __float2bfloat16(v.z), hw = __float2bfloat16(v.w);
    __nv_bfloat16 lx = __float2bfloat16(v.x - __bfloat162float(hx));
    __nv_bfloat16 ly = __float2bfloat16(v.y - __bfloat162float(hy));
    __nv_bfloat16 lz = __float2bfloat16(v.z - __bfloat162float(hz));
    __nv_bfloat16 lw = __float2bfloat16(v.w - __bfloat162float(hw));
    uint2 hi;
    hi.x = ((unsigned)__bfloat16_as_ushort(hy) << 16) | __bfloat16_as_ushort(hx);
    hi.y = ((unsigned)__bfloat16_as_ushort(hw) << 16) | __bfloat16_as_ushort(hz);
    lo.x = ((unsigned)__bfloat16_as_ushort(ly) << 16) | __bfloat16_as_ushort(lx);
    lo.y = ((unsigned)__bfloat16_as_ushort(lw) << 16) | __bfloat16_as_ushort(lz);
    return hi;
}

// -------- prep: halfnorm + bf16 hi/lo codebook splits + per-replay init --------
__global__ void prep_kernel(const float* __restrict__ cb) {
    int k = blockIdx.x, t = threadIdx.x;
    float v = cb[k * DD + t];
    __nv_bfloat16 h = __float2bfloat16(v);
    g_cbhi[k * DD + t] = h;
    g_cblo[k * DD + t] = __float2bfloat16(v - __bfloat162float(h));
    double s = (double)v * (double)v;
    #pragma unroll
    for (int o = 16; o > 0; o >>= 1) s += __shfl_xor_sync(0xffffffffu, s, o);
    __shared__ double sm[8];
    if ((t & 31) == 0) sm[t >> 5] = s;
    __syncthreads();
    if (t == 0) {
        double tot = 0.0;
        #pragma unroll
        for (int i = 0; i < 8; i++) tot += sm[i];
        g_hnd[k] = 0.5 * tot;
        g_halfnorm[k] = (float)(0.5 * tot);
        g_counts[k] = 0;
        if (k == 0) g_fixn = 0;
    }
}

__global__ void pad_kernel() {}

// -------- HMMA bf16-split scoring + per-row argmax(top-2) --------
// S = z_hi.c_hi + z_hi.c_lo + z_lo.c_hi (fp32 accum). score = S - 0.5||c||^2.
// CTA: 128 rows x 512 codes. A (z) converted ONCE into persistent smem
// (full K=256, hi+lo). B staged per 32-k tile with double-buffered cp.async.
__global__ __launch_bounds__(256) void argmin_tc_kernel(
        const float* __restrict__ z, float* __restrict__ enc_f, int row_base) {
    extern __shared__ __align__(16) unsigned char smem[];
    const unsigned sb = smem_u32(smem);
    const unsigned ahi = sb + SMO_AHI, alo = sb + SMO_ALO;
    float* shn = (float*)(smem + SMO_HN);

    int tid = threadIdx.x, wid = tid >> 5, l = tid & 31;
    int row0 = row_base + blockIdx.x * 128;

    shn[tid] = g_halfnorm[tid];
    shn[tid + 256] = g_halfnorm[tid + 256];

    // ---- issue B tile s=0 (chunk 0, kt 0) ----
    {
        #pragma unroll
        for (int i = 0; i < 4; i++) {
            int u = tid + i * 256;
            int split = u >> 9, uu = u & 511;
            int code = uu >> 2, c = uu & 3;
            const __nv_bfloat16* src = (split ? g_cblo : g_cbhi) + code * DD + c * 8;
            cp16(sb + SMO_B + split * SM_B_SPLIT + (unsigned)(code * PITCH_B + c * 16), src);
        }
        cp_commit();
    }

    // ---- convert A once: 128 rows x 256 k -> bf16 hi/lo, pitch 528 ----
    #pragma unroll
    for (int i = 0; i < 32; i++) {
        int u = tid + i * 256;            // 8192 float4 units
        int row = u >> 6, c = u & 63;
        float4 v = *(const float4*)(z + (long)(row0 + row) * DD + c * 4);
        uint2 lo, hi = bf16x4_hi(v, lo);
        unsigned off = (unsigned)(row * PITCH_A + c * 8);
        *(uint2*)(smem + SMO_AHI + off) = hi;
        *(uint2*)(smem + SMO_ALO + off) = lo;
    }

    // per-lane ldmatrix base offsets
    unsigned aoff = (unsigned)(((wid << 4) + (l & 15)) * PITCH_A + ((l >> 4) << 4));
    unsigned boff = (unsigned)((((l & 7) + ((l >> 4) << 3)) * PITCH_B) + (((l >> 3) & 1) << 4));

    float bv[2], sv[2]; int bi[2];
    bv[0] = bv[1] = -3.4e38f; sv[0] = sv[1] = -3.4e38f; bi[0] = bi[1] = 0;

    for (int chunk = 0; chunk < 4; chunk++) {
        int col0 = chunk * 128;
        float acc[16][4];
        #pragma unroll
        for (int n = 0; n < 16; n++)
            #pragma unroll
            for (int q = 0; q < 4; q++) acc[n][q] = 0.f;

        for (int kt = 0; kt < 8; kt++) {
            int s = chunk * 8 + kt;
            cp_wait_all();           // B tile s resident
            __syncthreads();         // visible to all warps; prev buf reads done
            if (s + 1 < 32) {        // prefetch tile s+1 into other buffer
                int ch1 = (s + 1) >> 3, kt1 = (s + 1) & 7;
                unsigned bb = sb + SMO_B + (unsigned)(((s + 1) & 1) * SM_B_BUF);
                #pragma unroll
                for (int i = 0; i < 4; i++) {
                    int u = tid + i * 256;
                    int split = u >> 9, uu = u & 511;
                    int code = uu >> 2, c = uu & 3;
                    const __nv_bfloat16* src = (split ? g_cblo : g_cbhi)
                        + (ch1 * 128 + code) * DD + kt1 * 32 + c * 8;
                    cp16(bb + (unsigned)(split * SM_B_SPLIT + code * PITCH_B + c * 16), src);
                }
                cp_commit();
            }
            unsigned bhi = sb + SMO_B + (unsigned)((s & 1) * SM_B_BUF);
            unsigned blo = bhi + SM_B_SPLIT;

            #pragma unroll
            for (int ks = 0; ks < 2; ks++) {
                unsigned akb = (unsigned)(kt * 64 + ks * 32);
                unsigned bkb = (unsigned)(ks << 5);
                unsigned ah[4], al[4];
                ldm_x4(ah, ahi + aoff + akb);
                ldm_x4(al, alo + aoff + akb);
                #pragma unroll
                for (int p = 0; p < 8; p++) {
                    unsigned bh[4], bl[4];
                    unsigned bo = boff + (unsigned)(p * 16 * PITCH_B) + bkb;
                    ldm_x4(bh, bhi + bo);
                    ldm_x4(bl, blo + bo);
                    mma16816(acc[2*p],   ah, bh[0], bh[1]);
                    mma16816(acc[2*p+1], ah, bh[2], bh[3]);
                    mma16816(acc[2*p],   ah, bl[0], bl[1]);
                    mma16816(acc[2*p+1], ah, bl[2], bl[3]);
                    mma16816(acc[2*p],   al, bh[0], bh[1]);
                    mma16816(acc[2*p+1], al, bh[2], bh[3]);
                }
            }
        }

        // epilogue: fold chunk scores into per-row top-2
        #pragma unroll
        for (int nt = 0; nt < 16; nt++) {
            int c0 = col0 + nt * 8 + ((l & 3) << 1);
            float2 hn2 = *(const float2*)&shn[c0];
            float s00 = acc[nt][0] - hn2.x, s01 = acc[nt][1] - hn2.y;
            float s10 = acc[nt][2] - hn2.x, s11 = acc[nt][3] - hn2.y;
            if (s00 > bv[0]) { sv[0] = bv[0]; bv[0] = s00; bi[0] = c0; }
            else if (s00 > sv[0]) sv[0] = s00;
            if (s01 > bv[0]) { sv[0] = bv[0]; bv[0] = s01; bi[0] = c0 + 1; }
            else if (s01 > sv[0]) sv[0] = s01;
            if (s10 > bv[1]) { sv[1] = bv[1]; bv[1] = s10; bi[1] = c0; }
            else if (s10 > sv[1]) sv[1] = s10;
            if (s11 > bv[1]) { sv[1] = bv[1]; bv[1] = s11; bi[1] = c0 + 1; }
            else if (s11 > sv[1]) sv[1] = s11;
        }
    }

    // reduce across the 4 lanes (l^1, l^2) sharing each row
    #pragma unroll
    for (int r = 0; r < 2; r++) {
        float v = bv[r], s2 = sv[r]; int idx = bi[r];
        #pragma unroll
        for (int off = 1; off <= 2; off <<= 1) {
            float v2  = __shfl_xor_sync(0xffffffffu, v, off);
            float s22 = __shfl_xor_sync(0xffffffffu, s2, off);
            int   i2  = __shfl_xor_sync(0xffffffffu, idx, off);
            if (v2 > v || (v2 == v && i2 < idx)) { s2 = fmaxf(v, s22); v = v2; idx = i2; }
            else { s2 = fmaxf(s2, v2); }
        }
        if ((l & 3) == 0) {
            int row = row0 + (wid << 4) + (l >> 2) + r * 8;
            g_enc[row] = idx;
            enc_f[row] = (float)idx;
            atomicAdd(&g_counts[idx], 1);
            if (v - s2 < 5e-4f) {
                int p = atomicAdd(&g_fixn, 1);
                if (p < 8192) g_fixrows[p] = row;
            }
        }
    }
}

// -------- exact fp64 re-argmax (dot form) for near-tie rows --------
__global__ void fixup_kernel(const float* __restrict__ z, const float* __restrict__ cb,
                             float* __restrict__ enc_f) {
    __shared__ double sval[256];
    __shared__ int    sidx[256];
    __shared__ float  zsh[DD];
    int nfix = min(g_fixn, 8192);
    int t = threadIdx.x;
    for (int e = blockIdx.x; e < nfix; e += gridDim.x) {
        int row = g_fixrows[e];
        zsh[t] = z[row * DD + t];
        __syncthreads();
        double bestv = -1e300; int besti = 0;
        #pragma unroll
        for (int kb = 0; kb < 2; kb++) {
            int k = t + kb * 256;
            const float* cr = cb + k * DD;
            double a0 = 0.0, a1 = 0.0, a2 = 0.0, a3 = 0.0;
            #pragma unroll 4
            for (int dd = 0; dd < DD; dd += 4) {
                a0 += (double)zsh[dd]     * (double)cr[dd];
                a1 += (double)zsh[dd + 1] * (double)cr[dd + 1];
                a2 += (double)zsh[dd + 2] * (double)cr[dd + 2];
                a3 += (double)zsh[dd + 3] * (double)cr[dd + 3];
            }
            double s = ((a0 + a1) + (a2 + a3)) - g_hnd[k];
            if (s > bestv || (s == bestv && k < besti)) { bestv = s; besti = k; }
        }
        sval[t] = bestv; sidx[t] = besti;
        __syncthreads();
        for (int off = 128; off > 0; off >>= 1) {
            if (t < off) {
                if (sval[t + off] > sval[t] ||
                    (sval[t + off] == sval[t] && sidx[t + off] < sidx[t])) {
                    sval[t] = sval[t + off]; sidx[t] = sidx[t + off];
                }
            }
            __syncthreads();
        }
        if (t == 0) {
            int old = g_enc[row];
            if (sidx[0] != old) {
                atomicSub(&g_counts[old], 1);
                atomicAdd(&g_counts[sidx[0]], 1);
                g_enc[row] = sidx[0];
                enc_f[row] = (float)sidx[0];
            }
        }
        __syncthreads();
    }
}

// -------- exclusive scan over 512 bins --------
__global__ void prefix_kernel() {
    __shared__ int a[KK];
    int t = threadIdx.x;
    int c = g_counts[t];
    a[t] = c;
    __syncthreads();
    for (int off = 1; off < KK; off <<= 1) {
        int v = (t >= off) ? a[t - off] : 0;
        __syncthreads();
        a[t] += v;
        __syncthreads();
    }
    int ex = a[t] - c;
    g_offsets[t] = ex;
    g_cursor[t] = ex;
}

// -------- scatter rows into per-code buckets --------
__global__ void scatter_kernel() {
    int stride = gridDim.x * blockDim.x;
    for (int i = blockIdx.x * blockDim.x + threadIdx.x; i < NR; i += stride) {
        int k = g_enc[i];
        int pos = atomicAdd(&g_cursor[k], 1);
        g_rowlist[pos] = i;
    }
}

// -------- per-code EMA: balanced partial sums --------
__global__ void update_partial_kernel(const float* __restrict__ z) {
    int k = blockIdx.x / NSEG, s = blockIdx.x % NSEG, t = threadIdx.x;
    int base = g_offsets[k];
    int cnt = g_counts[k];
    int lo = base + (int)((long long)cnt * s / NSEG);
    int hi = base + (int)((long long)cnt * (s + 1) / NSEG);
    float acc = 0.f;
    int i = lo;
    for (; i + 4 <= hi; i += 4) {
        int r0 = g_rowlist[i],     r1 = g_rowlist[i + 1];
        int r2 = g_rowlist[i + 2], r3 = g_rowlist[i + 3];
        float v0 = z[r0 * DD + t], v1 = z[r1 * DD + t];
        float v2 = z[r2 * DD + t], v3 = z[r3 * DD + t];
        acc += v0; acc += v1; acc += v2; acc += v3;
    }
    for (; i < hi; i++) acc += z[g_rowlist[i] * DD + t];
    g_epart[blockIdx.x * DD + t] = acc;
}

// -------- combine partials, write e_new / cb_new / n_new --------
__global__ void update_reduce_kernel(const float* __restrict__ n_i,
                                     const float* __restrict__ e_i,
                                     float* __restrict__ out_e, float* __restrict__ out_cb,
                                     float* __restrict__ out_n) {
    int k = blockIdx.x, t = threadIdx.x;
    const float* pp = g_epart + (k * NSEG) * DD + t;
    float acc = 0.f;
    #pragma unroll
    for (int i = 0; i < NSEG; i += 4) {
        float s01 = pp[i * DD] + pp[(i + 1) * DD];
        float s23 = pp[(i + 2) * DD] + pp[(i + 3) * DD];
        acc += s01 + s23;
    }
    const float C1 = (float)(1.0 - 0.99);
    const float NS = (float)(32.0 / (32.0 + 512.0 * 1e-5));
    float nnew = (0.99f * n_i[k] + C1 * (float)g_counts[k] + 1e-5f) * NS;
    float enew = 0.99f * e_i[k * DD + t] + C1 * acc;
    out_e[k * DD + t]  = enew;
    out_cb[k * DD + t] = enew / nnew;
    if (t == 0) out_n[k] = nnew;
}

// -------- gather codes, STE output, commitment-loss partials (linear z) -------
__global__ void gather_kernel(const float* __restrict__ z, const float* __restrict__ cb,
                              float* __restrict__ out_code) {
    float part = 0.f;
    int stride = gridDim.x * blockDim.x;
    for (int idx = blockIdx.x * blockDim.x + threadIdx.x; idx < NV4; idx += stride) {
        float4 zv = ((const float4*)z)[idx];
        int row = idx >> 6;
        int d = (idx & 63) << 2;
        int k = g_enc[row];
        float4 cv = *(const float4*)(cb + k * DD + d);
        float4 o;
        o.x = zv.x + (cv.x - zv.x);
        o.y = zv.y + (cv.y - zv.y);
        o.z = zv.z + (cv.z - zv.z);
        o.w = zv.w + (cv.w - zv.w);
        ((float4*)out_code)[idx] = o;
        float dx = zv.x - cv.x, dy = zv.y - cv.y;
        float dz = zv.z - cv.z, dw = zv.w - cv.w;
        part += dx * dx + dy * dy + dz * dz + dw * dw;
    }
    #pragma unroll
    for (int o = 16; o > 0; o >>= 1) part += __shfl_xor_sync(0xffffffffu, part, o);
    __shared__ float sm[8];
    if ((threadIdx.x & 31) == 0) sm[threadIdx.x >> 5] = part;
    __syncthreads();
    if (threadIdx.x == 0) {
        float tot = 0.f;
        #pragma unroll
        for (int i = 0; i < 8; i++) tot += sm[i];
        g_losspart[blockIdx.x] = (double)tot;
    }
}

__global__ void finalize_kernel(float* __restrict__ out_loss) {
    __shared__ double sm[256];
    double s = 0.0;
    for (int i = threadIdx.x; i < 8192; i += 256) s += g_losspart[i];
    sm[threadIdx.x] = s;
    __syncthreads();
    for (int off = 128; off > 0; off >>= 1) {
        if (threadIdx.x < off) sm[threadIdx.x] += sm[threadIdx.x + off];
        __syncthreads();
    }
    if (threadIdx.x == 0) out_loss[0] = 0.25f * (float)(sm[0] / 33554432.0);
}

extern "C" void kernel_launch(void* const* d_in, const int* in_sizes, int n_in,
                              void* d_out, int out_size) {
    const float* z   = (const float*)d_in[0];
    const float* cb  = (const float*)d_in[1];
    const float* n_i = (const float*)d_in[2];
    const float* e_i = (const float*)d_in[3];
    float* out = (float*)d_out;

    // idempotent attribute set (not a stream op; capture-safe)
    cudaFuncSetAttribute(argmin_tc_kernel,
                         cudaFuncAttributeMaxDynamicSharedMemorySize, SM_TOTAL);

    prep_kernel<<<KK, 256>>>(cb);                                      // #1
    pad_kernel<<<1, 32>>>();                                           // #2
    argmin_tc_kernel<<<512, 256, SM_TOTAL>>>(z, out + OFF_ENC, 0);     // #3 <- ncu
    argmin_tc_kernel<<<512, 256, SM_TOTAL>>>(z, out + OFF_ENC, 65536); // #4 <- ncu
    fixup_kernel<<<128, 256>>>(z, cb, out + OFF_ENC);                  // #5
    prefix_kernel<<<1, KK>>>();
    scatter_kernel<<<128, 256>>>();
    update_partial_kernel<<<KK * NSEG, 256>>>(z);
    update_reduce_kernel<<<KK, 256>>>(n_i, e_i, out + OFF_E, out + OFF_CB, out + OFF_N);
    gather_kernel<<<8192, 256>>>(z, cb, out);
    finalize_kernel<<<1, 256>>>(out + OFF_LOSS);
}

// round 11
// speedup vs baseline: 1.0493x; 1.0493x over previous
#include <cuda_runtime.h>
#include <cuda_bf16.h>

// Problem constants (fixed shapes per reference):
//   z: [32,256,64,64] f32 -> flat [131072, 256]
//   codebook: [512, 256], n_i: [512], e_i: [512,256]
#define NR 131072
#define DD 256
#define KK 512
#define NV4 (NR * DD / 4)

// Output layout (concatenated reference tuple, all float32):
#define OFF_LOSS 33554432
#define OFF_ENC  33554433
#define OFF_CB   33685505
#define OFF_N    33816577
#define OFF_E    33817089

#define NSEG 8
#define PITCH_B 80              // 32 bf16 (64B) + 16B pad: ldmatrix conflict-free
#define SM_STAGE 10240          // 128 * 80 bytes, one matrix-split tile
// per pipeline stage q: [AHI, ALO, BHI, BLO] x SM_STAGE
#define SMO_Q(q)  ((unsigned)(q) * 4u * SM_STAGE)
#define SMO_AHI   0
#define SMO_ALO   SM_STAGE
#define SMO_BHI   (2 * SM_STAGE)
#define SMO_BLO   (3 * SM_STAGE)
#define SMO_HN    (8 * SM_STAGE)          // 81920
#define SM_TOTAL  (SMO_HN + KK * 4)       // 83968 B -> 2 CTAs/SM in 228KB

// -------- device scratch (no allocations allowed) --------
static __device__ int    g_enc[NR];
static __device__ int    g_rowlist[NR];
static __device__ int    g_counts[KK];
static __device__ int    g_offsets[KK];
static __device__ int    g_cursor[KK];
static __device__ float  g_halfnorm[KK];
static __device__ double g_hnd[KK];
static __device__ int    g_fixn;
static __device__ int    g_fixrows[8192];
static __device__ float  g_epart[KK * NSEG * DD];
static __device__ double g_losspart[8192];
static __device__ __nv_bfloat16 g_cbhi[KK * DD];
static __device__ __nv_bfloat16 g_cblo[KK * DD];

// -------- PTX helpers --------
__device__ __forceinline__ unsigned smem_u32(const void* p) {
    unsigned a;
    asm("{ .reg .u64 t; cvta.to.shared.u64 t, %1; cvt.u32.u64 %0, t; }"
        : "=r"(a) : "l"(p));
    return a;
}
__device__ __forceinline__ void cp16(unsigned dst, const void* src) {
    asm volatile("cp.async.cg.shared.global [%0], [%1], 16;"
                 :: "r"(dst), "l"(__cvta_generic_to_global(src)));
}
__device__ __forceinline__ void cp_commit() { asm volatile("cp.async.commit_group;"); }
__device__ __forceinline__ void cp_wait_all() { asm volatile("cp.async.wait_group 0;"); }

__device__ __forceinline__ void ldm_x4(unsigned* r, unsigned addr) {
    asm volatile("ldmatrix.sync.aligned.m8n8.x4.shared.b16 {%0,%1,%2,%3}, [%4];"
                 : "=r"(r[0]), "=r"(r[1]), "=r"(r[2]), "=r"(r[3]) : "r"(addr));
}
__device__ __forceinline__ void mma16816(float* c, const unsigned* a,
                                         unsigned b0, unsigned b1) {
    asm volatile(
        "mma.sync.aligned.m16n8k16.row.col.f32.bf16.bf16.f32 "
        "{%0,%1,%2,%3}, {%4,%5,%6,%7}, {%8,%9}, {%0,%1,%2,%3};"
        : "+f"(c[0]), "+f"(c[1]), "+f"(c[2]), "+f"(c[3])
        : "r"(a[0]), "r"(a[1]), "r"(a[2]), "r"(a[3]), "r"(b0), "r"(b1));
}
__device__ __forceinline__ uint2 bf16x4_hi(float4 v, uint2& lo) {
    __nv_bfloat16 hx = __float2bfloat16(v.x), hy = __float2bfloat16(v.y);
    __nv_bfloat16 hz = __float2bfloat16(v.z), hw = __float2bfloat16(v.w);
    __nv_bfloat16 lx = __float2bfloat16(v.x - __bfloat162float(hx));
    __nv_bfloat16 ly = __float2bfloat16(v.y - __bfloat162float(hy));
    __nv_bfloat16 lz = __float2bfloat16(v.z - __bfloat162float(hz));
    __nv_bfloat16 lw = __float2bfloat16(v.w - __bfloat162float(hw));
    uint2 hi;
    hi.x = ((unsigned)__bfloat16_as_ushort(hy) << 16) | __bfloat16_as_ushort(hx);
    hi.y = ((unsigned)__bfloat16_as_ushort(hw) << 16) | __bfloat16_as_ushort(hz);
    lo.x = ((unsigned)__bfloat16_as_ushort(ly) << 16) | __bfloat16_as_ushort(lx);
    lo.y = ((unsigned)__bfloat16_as_ushort(lw) << 16) | __bfloat16_as_ushort(lz);
    return hi;
}

// -------- prep: halfnorm + bf16 hi/lo codebook splits + per-replay init --------
__global__ void prep_kernel(const float* __restrict__ cb) {
    int k = blockIdx.x, t = threadIdx.x;
    float v = cb[k * DD + t];
    __nv_bfloat16 h = __float2bfloat16(v);
    g_cbhi[k * DD + t] = h;
    g_cblo[k * DD + t] = __float2bfloat16(v - __bfloat162float(h));
    double s = (double)v * (double)v;
    #pragma unroll
    for (int o = 16; o > 0; o >>= 1) s += __shfl_xor_sync(0xffffffffu, s, o);
    __shared__ double sm[8];
    if ((t & 31) == 0) sm[t >> 5] = s;
    __syncthreads();
    if (t == 0) {
        double tot = 0.0;
        #pragma unroll
        for (int i = 0; i < 8; i++) tot += sm[i];
        g_hnd[k] = 0.5 * tot;
        g_halfnorm[k] = (float)(0.5 * tot);
        g_counts[k] = 0;
        if (k == 0) g_fixn = 0;
    }
}

__global__ void pad_kernel() {}

// -------- helpers for the pipelined argmin --------
__device__ __forceinline__ void stage_B(unsigned sb, int s, int tid) {
    int chunk = s >> 3, kt = s & 7;
    unsigned base = sb + SMO_Q(s & 1);
    #pragma unroll
    for (int i = 0; i < 4; i++) {
        int u = tid + i * 256;
        int split = u >> 9, uu = u & 511;
        int code = uu >> 2, c = uu & 3;
        const __nv_bfloat16* src = (split ? g_cblo : g_cbhi)
            + (chunk * 128 + code) * DD + kt * 32 + c * 8;
        cp16(base + (unsigned)((split ? SMO_BLO : SMO_BHI) + code * PITCH_B + c * 16), src);
    }
    cp_commit();
}
__device__ __forceinline__ void stage_A(unsigned char* smem, const float* z,
                                        int row0, int s, int tid) {
    int kt = s & 7;
    unsigned base = SMO_Q(s & 1);
    #pragma unroll 2
    for (int i = 0; i < 4; i++) {
        int u = tid + i * 256;              // 1024 float4 units
        int row = u >> 3, c = u & 7;
        float4 v = *(const float4*)(z + (long)(row0 + row) * DD + kt * 32 + c * 4);
        uint2 lo, hi = bf16x4_hi(v, lo);
        unsigned off = base + (unsigned)(row * PITCH_B + c * 8);
        *(uint2*)(smem + SMO_AHI + off) = hi;
        *(uint2*)(smem + SMO_ALO + off) = lo;
    }
}

// -------- HMMA bf16-split scoring + per-row argmax(top-2), pipelined --------
// S = z_hi.c_hi + z_hi.c_lo + z_lo.c_hi (fp32 accum). score = S - 0.5||c||^2.
// CTA: 128 rows x 512 codes; 32 K-tiles (4 col-chunks x 8 kt). Double-buffered
// stages; ONE barrier per tile; B cp.async + A convert overlap tile-s MMAs.
__global__ __launch_bounds__(256, 2) void argmin_tc_kernel(
        const float* __restrict__ z, float* __restrict__ enc_f, int row_base) {
    extern __shared__ __align__(16) unsigned char smem[];
    const unsigned sb = smem_u32(smem);
    float* shn = (float*)(smem + SMO_HN);

    int tid = threadIdx.x, wid = tid >> 5, l = tid & 31;
    int row0 = row_base + blockIdx.x * 128;

    shn[tid] = g_halfnorm[tid];
    shn[tid + 256] = g_halfnorm[tid + 256];

    // prologue: stage tile 0
    stage_B(sb, 0, tid);
    stage_A(smem, z, row0, 0, tid);

    // per-lane ldmatrix base offsets (within a stage tile, pitch 80)
    unsigned aoff = (unsigned)(((wid << 4) + (l & 15)) * PITCH_B + ((l >> 4) << 4));
    unsigned boff = (unsigned)((((l & 7) + ((l >> 4) << 3)) * PITCH_B) + (((l >> 3) & 1) << 4));

    float bv[2], sv[2]; int bi[2];
    bv[0] = bv[1] = -3.4e38f; sv[0] = sv[1] = -3.4e38f; bi[0] = bi[1] = 0;

    float acc[16][4];
    #pragma unroll
    for (int n = 0; n < 16; n++)
        #pragma unroll
        for (int q = 0; q < 4; q++) acc[n][q] = 0.f;

    for (int s = 0; s < 32; s++) {
        cp_wait_all();           // B(s) resident (only pending group)
        __syncthreads();         // A(s)/B(s) visible; compute s-1 done (alt buf free)
        if (s + 1 < 32) {        // stage tile s+1 into alternate buffer (overlaps MMA)
            stage_B(sb, s + 1, tid);
            stage_A(smem, z, row0, s + 1, tid);
        }
        unsigned qb = SMO_Q(s & 1);
        unsigned ahi = sb + qb + SMO_AHI, alo = sb + qb + SMO_ALO;
        unsigned bhi = sb + qb + SMO_BHI, blo = sb + qb + SMO_BLO;

        #pragma unroll
        for (int ks = 0; ks < 2; ks++) {
            unsigned kb = (unsigned)(ks << 5);
            unsigned ah[4], al[4];
            ldm_x4(ah, ahi + aoff + kb);
            ldm_x4(al, alo + aoff + kb);
            #pragma unroll
            for (int p = 0; p < 8; p++) {
                unsigned bh[4], bl[4];
                unsigned bo = boff + (unsigned)(p * 16 * PITCH_B) + kb;
                ldm_x4(bh, bhi + bo);
                ldm_x4(bl, blo + bo);
                mma16816(acc[2*p],   ah, bh[0], bh[1]);
                mma16816(acc[2*p+1], ah, bh[2], bh[3]);
                mma16816(acc[2*p],   ah, bl[0], bl[1]);
                mma16816(acc[2*p+1], ah, bl[2], bl[3]);
                mma16816(acc[2*p],   al, bh[0], bh[1]);
                mma16816(acc[2*p+1], al, bh[2], bh[3]);
            }
        }

        if ((s & 7) == 7) {      // end of col-chunk: fold scores into top-2
            int col0 = (s >> 3) * 128;
            #pragma unroll
            for (int nt = 0; nt < 16; nt++) {
                int c0 = col0 + nt * 8 + ((l & 3) << 1);
                float2 hn2 = *(const float2*)&shn[c0];
                float s00 = acc[nt][0] - hn2.x, s01 = acc[nt][1] - hn2.y;
                float s10 = acc[nt][2] - hn2.x, s11 = acc[nt][3] - hn2.y;
                if (s00 > bv[0]) { sv[0] = bv[0]; bv[0] = s00; bi[0] = c0; }
                else if (s00 > sv[0]) sv[0] = s00;
                if (s01 > bv[0]) { sv[0] = bv[0]; bv[0] = s01; bi[0] = c0 + 1; }
                else if (s01 > sv[0]) sv[0] = s01;
                if (s10 > bv[1]) { sv[1] = bv[1]; bv[1] = s10; bi[1] = c0; }
                else if (s10 > sv[1]) sv[1] = s10;
                if (s11 > bv[1]) { sv[1] = bv[1]; bv[1] = s11; bi[1] = c0 + 1; }
                else if (s11 > sv[1]) sv[1] = s11;
            }
            #pragma unroll
            for (int nt = 0; nt < 16; nt++)
                #pragma unroll
                for (int q = 0; q < 4; q++) acc[nt][q] = 0.f;
        }
    }

    // reduce across the 4 lanes (l^1, l^2) sharing each row
    #pragma unroll
    for (int r = 0; r < 2; r++) {
        float v = bv[r], s2 = sv[r]; int idx = bi[r];
        #pragma unroll
        for (int off = 1; off <= 2; off <<= 1) {
            float v2  = __shfl_xor_sync(0xffffffffu, v, off);
            float s22 = __shfl_xor_sync(0xffffffffu, s2, off);
            int   i2  = __shfl_xor_sync(0xffffffffu, idx, off);
            if (v2 > v || (v2 == v && i2 < idx)) { s2 = fmaxf(v, s22); v = v2; idx = i2; }
            else { s2 = fmaxf(s2, v2); }
        }
        if ((l & 3) == 0) {
            int row = row0 + (wid << 4) + (l >> 2) + r * 8;
            g_enc[row] = idx;
            enc_f[row] = (float)idx;
            atomicAdd(&g_counts[idx], 1);
            if (v - s2 < 5e-4f) {
                int p = atomicAdd(&g_fixn, 1);
                if (p < 8192) g_fixrows[p] = row;
            }
        }
    }
}

// -------- exact fp64 re-argmax (dot form) for near-tie rows --------
__global__ void fixup_kernel(const float* __restrict__ z, const float* __restrict__ cb,
                             float* __restrict__ enc_f) {
    __shared__ double sval[256];
    __shared__ int    sidx[256];
    __shared__ float  zsh[DD];
    int nfix = min(g_fixn, 8192);
    int t = threadIdx.x;
    for (int e = blockIdx.x; e < nfix; e += gridDim.x) {
        int row = g_fixrows[e];
        zsh[t] = z[row * DD + t];
        __syncthreads();
        double bestv = -1e300; int besti = 0;
        #pragma unroll
        for (int kb = 0; kb < 2; kb++) {
            int k = t + kb * 256;
            const float* cr = cb + k * DD;
            double a0 = 0.0, a1 = 0.0, a2 = 0.0, a3 = 0.0;
            #pragma unroll 4
            for (int dd = 0; dd < DD; dd += 4) {
                a0 += (double)zsh[dd]     * (double)cr[dd];
                a1 += (double)zsh[dd + 1] * (double)cr[dd + 1];
                a2 += (double)zsh[dd + 2] * (double)cr[dd + 2];
                a3 += (double)zsh[dd + 3] * (double)cr[dd + 3];
            }
            double s = ((a0 + a1) + (a2 + a3)) - g_hnd[k];
            if (s > bestv || (s == bestv && k < besti)) { bestv = s; besti = k; }
        }
        sval[t] = bestv; sidx[t] = besti;
        __syncthreads();
        for (int off = 128; off > 0; off >>= 1) {
            if (t < off) {
                if (sval[t + off] > sval[t] ||
                    (sval[t + off] == sval[t] && sidx[t + off] < sidx[t])) {
                    sval[t] = sval[t + off]; sidx[t] = sidx[t + off];
                }
            }
            __syncthreads();
        }
        if (t == 0) {
            int old = g_enc[row];
            if (sidx[0] != old) {
                atomicSub(&g_counts[old], 1);
                atomicAdd(&g_counts[sidx[0]], 1);
                g_enc[row] = sidx[0];
                enc_f[row] = (float)sidx[0];
            }
        }
        __syncthreads();
    }
}

// -------- exclusive scan over 512 bins --------
__global__ void prefix_kernel() {
    __shared__ int a[KK];
    int t = threadIdx.x;
    int c = g_counts[t];
    a[t] = c;
    __syncthreads();
    for (int off = 1; off < KK; off <<= 1) {
        int v = (t >= off) ? a[t - off] : 0;
        __syncthreads();
        a[t] += v;
        __syncthreads();
    }
    int ex = a[t] - c;
    g_offsets[t] = ex;
    g_cursor[t] = ex;
}

// -------- scatter rows into per-code buckets --------
__global__ void scatter_kernel() {
    int stride = gridDim.x * blockDim.x;
    for (int i = blockIdx.x * blockDim.x + threadIdx.x; i < NR; i += stride) {
        int k = g_enc[i];
        int pos = atomicAdd(&g_cursor[k], 1);
        g_rowlist[pos] = i;
    }
}

// -------- per-code EMA: balanced partial sums --------
__global__ void update_partial_kernel(const float* __restrict__ z) {
    int k = blockIdx.x / NSEG, s = blockIdx.x % NSEG, t = threadIdx.x;
    int base = g_offsets[k];
    int cnt = g_counts[k];
    int lo = base + (int)((long long)cnt * s / NSEG);
    int hi = base + (int)((long long)cnt * (s + 1) / NSEG);
    float acc = 0.f;
    int i = lo;
    for (; i + 4 <= hi; i += 4) {
        int r0 = g_rowlist[i],     r1 = g_rowlist[i + 1];
        int r2 = g_rowlist[i + 2], r3 = g_rowlist[i + 3];
        float v0 = z[r0 * DD + t], v1 = z[r1 * DD + t];
        float v2 = z[r2 * DD + t], v3 = z[r3 * DD + t];
        acc += v0; acc += v1; acc += v2; acc += v3;
    }
    for (; i < hi; i++) acc += z[g_rowlist[i] * DD + t];
    g_epart[blockIdx.x * DD + t] = acc;
}

// -------- combine partials, write e_new / cb_new / n_new --------
__global__ void update_reduce_kernel(const float* __restrict__ n_i,
                                     const float* __restrict__ e_i,
                                     float* __restrict__ out_e, float* __restrict__ out_cb,
                                     float* __restrict__ out_n) {
    int k = blockIdx.x, t = threadIdx.x;
    const float* pp = g_epart + (k * NSEG) * DD + t;
    float acc = 0.f;
    #pragma unroll
    for (int i = 0; i < NSEG; i += 4) {
        float s01 = pp[i * DD] + pp[(i + 1) * DD];
        float s23 = pp[(i + 2) * DD] + pp[(i + 3) * DD];
        acc += s01 + s23;
    }
    const float C1 = (float)(1.0 - 0.99);
    const float NS = (float)(32.0 / (32.0 + 512.0 * 1e-5));
    float nnew = (0.99f * n_i[k] + C1 * (float)g_counts[k] + 1e-5f) * NS;
    float enew = 0.99f * e_i[k * DD + t] + C1 * acc;
    out_e[k * DD + t]  = enew;
    out_cb[k * DD + t] = enew / nnew;
    if (t == 0) out_n[k] = nnew;
}

// -------- gather codes, STE output, commitment-loss partials (linear z) -------
__global__ void gather_kernel(const float* __restrict__ z, const float* __restrict__ cb,
                              float* __restrict__ out_code) {
    float part = 0.f;
    int stride = gridDim.x * blockDim.x;
    for (int idx = blockIdx.x * blockDim.x + threadIdx.x; idx < NV4; idx += stride) {
        float4 zv = ((const float4*)z)[idx];
        int row = idx >> 6;
        int d = (idx & 63) << 2;
        int k = g_enc[row];
        float4 cv = *(const float4*)(cb + k * DD + d);
        float4 o;
        o.x = zv.x + (cv.x - zv.x);
        o.y = zv.y + (cv.y - zv.y);
        o.z = zv.z + (cv.z - zv.z);
        o.w = zv.w + (cv.w - zv.w);
        ((float4*)out_code)[idx] = o;
        float dx = zv.x - cv.x, dy = zv.y - cv.y;
        float dz = zv.z - cv.z, dw = zv.w - cv.w;
        part += dx * dx + dy * dy + dz * dz + dw * dw;
    }
    #pragma unroll
    for (int o = 16; o > 0; o >>= 1) part += __shfl_xor_sync(0xffffffffu, part, o);
    __shared__ float sm[8];
    if ((threadIdx.x & 31) == 0) sm[threadIdx.x >> 5] = part;
    __syncthreads();
    if (threadIdx.x == 0) {
        float tot = 0.f;
        #pragma unroll
        for (int i = 0; i < 8; i++) tot += sm[i];
        g_losspart[blockIdx.x] = (double)tot;
    }
}

__global__ void finalize_kernel(float* __restrict__ out_loss) {
    __shared__ double sm[256];
    double s = 0.0;
    for (int i = threadIdx.x; i < 8192; i += 256) s += g_losspart[i];
    sm[threadIdx.x] = s;
    __syncthreads();
    for (int off = 128; off > 0; off >>= 1) {
        if (threadIdx.x < off) sm[threadIdx.x] += sm[threadIdx.x + off];
        __syncthreads();
    }
    if (threadIdx.x == 0) out_loss[0] = 0.25f * (float)(sm[0] / 33554432.0);
}

extern "C" void kernel_launch(void* const* d_in, const int* in_sizes, int n_in,
                              void* d_out, int out_size) {
    const float* z   = (const float*)d_in[0];
    const float* cb  = (const float*)d_in[1];
    const float* n_i = (const float*)d_in[2];
    const float* e_i = (const float*)d_in[3];
    float* out = (float*)d_out;

    // idempotent attribute set (not a stream op; capture-safe)
    cudaFuncSetAttribute(argmin_tc_kernel,
                         cudaFuncAttributeMaxDynamicSharedMemorySize, SM_TOTAL);

    prep_kernel<<<KK, 256>>>(cb);                                      // #1
    pad_kernel<<<1, 32>>>();                                           // #2
    argmin_tc_kernel<<<512, 256, SM_TOTAL>>>(z, out + OFF_ENC, 0);     // #3 <- ncu
    argmin_tc_kernel<<<512, 256, SM_TOTAL>>>(z, out + OFF_ENC, 65536); // #4 <- ncu
    fixup_kernel<<<128, 256>>>(z, cb, out + OFF_ENC);                  // #5
    prefix_kernel<<<1, KK>>>();
    scatter_kernel<<<128, 256>>>();
    update_partial_kernel<<<KK * NSEG, 256>>>(z);
    update_reduce_kernel<<<KK, 256>>>(n_i, e_i, out + OFF_E, out + OFF_CB, out + OFF_N);
    gather_kernel<<<8192, 256>>>(z, cb, out);
    finalize_kernel<<<1, 256>>>(out + OFF_LOSS);
}

// round 12
// speedup vs baseline: 1.0931x; 1.0417x over previous
#include <cuda_runtime.h>
#include <cuda_bf16.h>

// Problem constants (fixed shapes per reference):
//   z: [32,256,64,64] f32 -> flat [131072, 256]
//   codebook: [512, 256], n_i: [512], e_i: [512,256]
#define NR 131072
#define DD 256
#define KK 512
#define NV4 (NR * DD / 4)

// Output layout (concatenated reference tuple, all float32):
#define OFF_LOSS 33554432
#define OFF_ENC  33554433
#define OFF_CB   33685505
#define OFF_N    33816577
#define OFF_E    33817089

#define NSEG 8
#define PITCH_B 80              // 32 bf16 (64B) + 16B pad: ldmatrix conflict-free
#define SM_STAGE 10240          // 128 * 80 bytes, one matrix-split tile
// per pipeline stage q: [AHI, ALO, BHI, BLO] x SM_STAGE
#define SMO_Q(q)  ((unsigned)(q) * 4u * SM_STAGE)
#define SMO_AHI   0
#define SMO_ALO   SM_STAGE
#define SMO_BHI   (2 * SM_STAGE)
#define SMO_BLO   (3 * SM_STAGE)
#define SMO_HN    (8 * SM_STAGE)          // 81920
#define SM_TOTAL  (SMO_HN + KK * 4)       // 83968 B -> 2 CTAs/SM in 228KB

// -------- device scratch (no allocations allowed) --------
static __device__ int    g_enc[NR];
static __device__ int    g_rowlist[NR];
static __device__ int    g_counts[KK];
static __device__ int    g_offsets[KK];
static __device__ int    g_cursor[KK];
static __device__ float  g_halfnorm[KK];
static __device__ double g_hnd[KK];
static __device__ int    g_fixn;
static __device__ int    g_fixrows[8192];
static __device__ float  g_epart[KK * NSEG * DD];
static __device__ double g_losspart[8192];
static __device__ __nv_bfloat16 g_cbhi[KK * DD];
static __device__ __nv_bfloat16 g_cblo[KK * DD];

// -------- PTX helpers --------
__device__ __forceinline__ unsigned smem_u32(const void* p) {
    unsigned a;
    asm("{ .reg .u64 t; cvta.to.shared.u64 t, %1; cvt.u32.u64 %0, t; }"
        : "=r"(a) : "l"(p));
    return a;
}
__device__ __forceinline__ void cp16(unsigned dst, const void* src) {
    asm volatile("cp.async.cg.shared.global [%0], [%1], 16;"
                 :: "r"(dst), "l"(__cvta_generic_to_global(src)));
}
__device__ __forceinline__ void cp_commit() { asm volatile("cp.async.commit_group;"); }
__device__ __forceinline__ void cp_wait_all() { asm volatile("cp.async.wait_group 0;"); }

__device__ __forceinline__ void ldm_x4(unsigned* r, unsigned addr) {
    asm volatile("ldmatrix.sync.aligned.m8n8.x4.shared.b16 {%0,%1,%2,%3}, [%4];"
                 : "=r"(r[0]), "=r"(r[1]), "=r"(r[2]), "=r"(r[3]) : "r"(addr));
}
__device__ __forceinline__ void mma16816(float* c, const unsigned* a,
                                         unsigned b0, unsigned b1) {
    asm volatile(
        "mma.sync.aligned.m16n8k16.row.col.f32.bf16.bf16.f32 "
        "{%0,%1,%2,%3}, {%4,%5,%6,%7}, {%8,%9}, {%0,%1,%2,%3};"
        : "+f"(c[0]), "+f"(c[1]), "+f"(c[2]), "+f"(c[3])
        : "r"(a[0]), "r"(a[1]), "r"(a[2]), "r"(a[3]), "r"(b0), "r"(b1));
}
__device__ __forceinline__ uint2 bf16x4_hi(float4 v, uint2& lo) {
    __nv_bfloat16 hx = __float2bfloat16(v.x), hy = __float2bfloat16(v.y);
    __nv_bfloat16 hz = __float2bfloat16(v.z), hw = __float2bfloat16(v.w);
    __nv_bfloat16 lx = __float2bfloat16(v.x - __bfloat162float(hx));
    __nv_bfloat16 ly = __float2bfloat16(v.y - __bfloat162float(hy));
    __nv_bfloat16 lz = __float2bfloat16(v.z - __bfloat162float(hz));
    __nv_bfloat16 lw = __float2bfloat16(v.w - __bfloat162float(hw));
    uint2 hi;
    hi.x = ((unsigned)__bfloat16_as_ushort(hy) << 16) | __bfloat16_as_ushort(hx);
    hi.y = ((unsigned)__bfloat16_as_ushort(hw) << 16) | __bfloat16_as_ushort(hz);
    lo.x = ((unsigned)__bfloat16_as_ushort(ly) << 16) | __bfloat16_as_ushort(lx);
    lo.y = ((unsigned)__bfloat16_as_ushort(lw) << 16) | __bfloat16_as_ushort(lz);
    return hi;
}

// -------- prep: halfnorm + bf16 hi/lo codebook splits + per-replay init --------
__global__ void prep_kernel(const float* __restrict__ cb) {
    int k = blockIdx.x, t = threadIdx.x;
    float v = cb[k * DD + t];
    __nv_bfloat16 h = __float2bfloat16(v);
    g_cbhi[k * DD + t] = h;
    g_cblo[k * DD + t] = __float2bfloat16(v - __bfloat162float(h));
    double s = (double)v * (double)v;
    #pragma unroll
    for (int o = 16; o > 0; o >>= 1) s += __shfl_xor_sync(0xffffffffu, s, o);
    __shared__ double sm[8];
    if ((t & 31) == 0) sm[t >> 5] = s;
    __syncthreads();
    if (t == 0) {
        double tot = 0.0;
        #pragma unroll
        for (int i = 0; i < 8; i++) tot += sm[i];
        g_hnd[k] = 0.5 * tot;
        g_halfnorm[k] = (float)(0.5 * tot);
        g_counts[k] = 0;
        if (k == 0) g_fixn = 0;
    }
}

__global__ void pad_kernel() {}

// -------- helpers for the pipelined argmin --------
__device__ __forceinline__ void stage_B(unsigned sb, int s, int tid) {
    int chunk = s >> 3, kt = s & 7;
    unsigned base = sb + SMO_Q(s & 1);
    #pragma unroll
    for (int i = 0; i < 4; i++) {
        int u = tid + i * 256;
        int split = u >> 9, uu = u & 511;
        int code = uu >> 2, c = uu & 3;
        const __nv_bfloat16* src = (split ? g_cblo : g_cbhi)
            + (chunk * 128 + code) * DD + kt * 32 + c * 8;
        cp16(base + (unsigned)((split ? SMO_BLO : SMO_BHI) + code * PITCH_B + c * 16), src);
    }
    cp_commit();
}
__device__ __forceinline__ void stage_A(unsigned char* smem, const float* z,
                                        int row0, int s, int tid) {
    int kt = s & 7;
    unsigned base = SMO_Q(s & 1);
    #pragma unroll 2
    for (int i = 0; i < 4; i++) {
        int u = tid + i * 256;              // 1024 float4 units
        int row = u >> 3, c = u & 7;
        float4 v = *(const float4*)(z + (long)(row0 + row) * DD + kt * 32 + c * 4);
        uint2 lo, hi = bf16x4_hi(v, lo);
        unsigned off = base + (unsigned)(row * PITCH_B + c * 8);
        *(uint2*)(smem + SMO_AHI + off) = hi;
        *(uint2*)(smem + SMO_ALO + off) = lo;
    }
}

// -------- HMMA bf16-split scoring + per-row argmax(top-2), pipelined --------
// S = z_hi.c_hi + z_hi.c_lo + z_lo.c_hi (fp32 accum). score = S - 0.5||c||^2.
// CTA: 128 rows x 512 codes; 32 K-tiles (4 col-chunks x 8 kt). Double-buffered
// stages. Inner loop batches 2 p-iterations: 4 B-LDSM then 12 MMAs ordered so
// same-acc MMAs are 4 issues apart (4 independent dependency chains).
__global__ __launch_bounds__(256, 2) void argmin_tc_kernel(
        const float* __restrict__ z, float* __restrict__ enc_f) {
    extern __shared__ __align__(16) unsigned char smem[];
    const unsigned sb = smem_u32(smem);
    float* shn = (float*)(smem + SMO_HN);

    int tid = threadIdx.x, wid = tid >> 5, l = tid & 31;
    int row0 = blockIdx.x * 128;

    shn[tid] = g_halfnorm[tid];
    shn[tid + 256] = g_halfnorm[tid + 256];

    // prologue: stage tile 0
    stage_B(sb, 0, tid);
    stage_A(smem, z, row0, 0, tid);

    // per-lane ldmatrix base offsets (within a stage tile, pitch 80)
    unsigned aoff = (unsigned)(((wid << 4) + (l & 15)) * PITCH_B + ((l >> 4) << 4));
    unsigned boff = (unsigned)((((l & 7) + ((l >> 4) << 3)) * PITCH_B) + (((l >> 3) & 1) << 4));

    float bv[2], sv[2]; int bi[2];
    bv[0] = bv[1] = -3.4e38f; sv[0] = sv[1] = -3.4e38f; bi[0] = bi[1] = 0;

    float acc[16][4];
    #pragma unroll
    for (int n = 0; n < 16; n++)
        #pragma unroll
        for (int q = 0; q < 4; q++) acc[n][q] = 0.f;

    for (int s = 0; s < 32; s++) {
        cp_wait_all();           // B(s) resident (only pending group)
        __syncthreads();         // A(s)/B(s) visible; compute s-1 done (alt buf free)
        if (s + 1 < 32) {        // stage tile s+1 into alternate buffer (overlaps MMA)
            stage_B(sb, s + 1, tid);
            stage_A(smem, z, row0, s + 1, tid);
        }
        unsigned qb = SMO_Q(s & 1);
        unsigned ahi = sb + qb + SMO_AHI, alo = sb + qb + SMO_ALO;
        unsigned bhi = sb + qb + SMO_BHI, blo = sb + qb + SMO_BLO;

        #pragma unroll
        for (int ks = 0; ks < 2; ks++) {
            unsigned kb = (unsigned)(ks << 5);
            unsigned ah[4], al[4];
            ldm_x4(ah, ahi + aoff + kb);
            ldm_x4(al, alo + aoff + kb);
            #pragma unroll
            for (int pp = 0; pp < 4; pp++) {       // 2 p's per batch
                unsigned bha[4], bla[4], bhb[4], blb[4];
                unsigned boa = boff + (unsigned)((2 * pp) * 16 * PITCH_B) + kb;
                unsigned bob = boa + (unsigned)(16 * PITCH_B);
                ldm_x4(bha, bhi + boa);
                ldm_x4(bla, blo + boa);
                ldm_x4(bhb, bhi + bob);
                ldm_x4(blb, blo + bob);
                float* A0 = acc[4 * pp];     float* A1 = acc[4 * pp + 1];
                float* A2 = acc[4 * pp + 2]; float* A3 = acc[4 * pp + 3];
                // 12 MMAs, same-acc spaced 4 apart
                mma16816(A0, ah, bha[0], bha[1]);
                mma16816(A1, ah, bha[2], bha[3]);
                mma16816(A2, ah, bhb[0], bhb[1]);
                mma16816(A3, ah, bhb[2], bhb[3]);
                mma16816(A0, ah, bla[0], bla[1]);
                mma16816(A1, ah, bla[2], bla[3]);
                mma16816(A2, ah, blb[0], blb[1]);
                mma16816(A3, ah, blb[2], blb[3]);
                mma16816(A0, al, bha[0], bha[1]);
                mma16816(A1, al, bha[2], bha[3]);
                mma16816(A2, al, bhb[0], bhb[1]);
                mma16816(A3, al, bhb[2], bhb[3]);
            }
        }

        if ((s & 7) == 7) {      // end of col-chunk: fold scores into top-2
            int col0 = (s >> 3) * 128;
            #pragma unroll
            for (int nt = 0; nt < 16; nt++) {
                int c0 = col0 + nt * 8 + ((l & 3) << 1);
                float2 hn2 = *(const float2*)&shn[c0];
                float s00 = acc[nt][0] - hn2.x, s01 = acc[nt][1] - hn2.y;
                float s10 = acc[nt][2] - hn2.x, s11 = acc[nt][3] - hn2.y;
                if (s00 > bv[0]) { sv[0] = bv[0]; bv[0] = s00; bi[0] = c0; }
                else if (s00 > sv[0]) sv[0] = s00;
                if (s01 > bv[0]) { sv[0] = bv[0]; bv[0] = s01; bi[0] = c0 + 1; }
                else if (s01 > sv[0]) sv[0] = s01;
                if (s10 > bv[1]) { sv[1] = bv[1]; bv[1] = s10; bi[1] = c0; }
                else if (s10 > sv[1]) sv[1] = s10;
                if (s11 > bv[1]) { sv[1] = bv[1]; bv[1] = s11; bi[1] = c0 + 1; }
                else if (s11 > sv[1]) sv[1] = s11;
            }
            #pragma unroll
            for (int nt = 0; nt < 16; nt++)
                #pragma unroll
                for (int q = 0; q < 4; q++) acc[nt][q] = 0.f;
        }
    }

    // reduce across the 4 lanes (l^1, l^2) sharing each row
    #pragma unroll
    for (int r = 0; r < 2; r++) {
        float v = bv[r], s2 = sv[r]; int idx = bi[r];
        #pragma unroll
        for (int off = 1; off <= 2; off <<= 1) {
            float v2  = __shfl_xor_sync(0xffffffffu, v, off);
            float s22 = __shfl_xor_sync(0xffffffffu, s2, off);
            int   i2  = __shfl_xor_sync(0xffffffffu, idx, off);
            if (v2 > v || (v2 == v && i2 < idx)) { s2 = fmaxf(v, s22); v = v2; idx = i2; }
            else { s2 = fmaxf(s2, v2); }
        }
        if ((l & 3) == 0) {
            int row = row0 + (wid << 4) + (l >> 2) + r * 8;
            g_enc[row] = idx;
            enc_f[row] = (float)idx;
            atomicAdd(&g_counts[idx], 1);
            if (v - s2 < 5e-4f) {
                int p = atomicAdd(&g_fixn, 1);
                if (p < 8192) g_fixrows[p] = row;
            }
        }
    }
}

// -------- exact fp64 re-argmax (dot form) for near-tie rows --------
__global__ void fixup_kernel(const float* __restrict__ z, const float* __restrict__ cb,
                             float* __restrict__ enc_f) {
    __shared__ double sval[256];
    __shared__ int    sidx[256];
    __shared__ float  zsh[DD];
    int nfix = min(g_fixn, 8192);
    int t = threadIdx.x;
    for (int e = blockIdx.x; e < nfix; e += gridDim.x) {
        int row = g_fixrows[e];
        zsh[t] = z[row * DD + t];
        __syncthreads();
        double bestv = -1e300; int besti = 0;
        #pragma unroll
        for (int kb = 0; kb < 2; kb++) {
            int k = t + kb * 256;
            const float* cr = cb + k * DD;
            double a0 = 0.0, a1 = 0.0, a2 = 0.0, a3 = 0.0;
            #pragma unroll 4
            for (int dd = 0; dd < DD; dd += 4) {
                a0 += (double)zsh[dd]     * (double)cr[dd];
                a1 += (double)zsh[dd + 1] * (double)cr[dd + 1];
                a2 += (double)zsh[dd + 2] * (double)cr[dd + 2];
                a3 += (double)zsh[dd + 3] * (double)cr[dd + 3];
            }
            double s = ((a0 + a1) + (a2 + a3)) - g_hnd[k];
            if (s > bestv || (s == bestv && k < besti)) { bestv = s; besti = k; }
        }
        sval[t] = bestv; sidx[t] = besti;
        __syncthreads();
        for (int off = 128; off > 0; off >>= 1) {
            if (t < off) {
                if (sval[t + off] > sval[t] ||
                    (sval[t + off] == sval[t] && sidx[t + off] < sidx[t])) {
                    sval[t] = sval[t + off]; sidx[t] = sidx[t + off];
                }
            }
            __syncthreads();
        }
        if (t == 0) {
            int old = g_enc[row];
            if (sidx[0] != old) {
                atomicSub(&g_counts[old], 1);
                atomicAdd(&g_counts[sidx[0]], 1);
                g_enc[row] = sidx[0];
                enc_f[row] = (float)sidx[0];
            }
        }
        __syncthreads();
    }
}

// -------- exclusive scan over 512 bins --------
__global__ void prefix_kernel() {
    __shared__ int a[KK];
    int t = threadIdx.x;
    int c = g_counts[t];
    a[t] = c;
    __syncthreads();
    for (int off = 1; off < KK; off <<= 1) {
        int v = (t >= off) ? a[t - off] : 0;
        __syncthreads();
        a[t] += v;
        __syncthreads();
    }
    int ex = a[t] - c;
    g_offsets[t] = ex;
    g_cursor[t] = ex;
}

// -------- scatter rows into per-code buckets --------
__global__ void scatter_kernel() {
    int stride = gridDim.x * blockDim.x;
    for (int i = blockIdx.x * blockDim.x + threadIdx.x; i < NR; i += stride) {
        int k = g_enc[i];
        int pos = atomicAdd(&g_cursor[k], 1);
        g_rowlist[pos] = i;
    }
}

// -------- per-code EMA: balanced partial sums --------
__global__ void update_partial_kernel(const float* __restrict__ z) {
    int k = blockIdx.x / NSEG, s = blockIdx.x % NSEG, t = threadIdx.x;
    int base = g_offsets[k];
    int cnt = g_counts[k];
    int lo = base + (int)((long long)cnt * s / NSEG);
    int hi = base + (int)((long long)cnt * (s + 1) / NSEG);
    float acc = 0.f;
    int i = lo;
    for (; i + 4 <= hi; i += 4) {
        int r0 = g_rowlist[i],     r1 = g_rowlist[i + 1];
        int r2 = g_rowlist[i + 2], r3 = g_rowlist[i + 3];
        float v0 = z[r0 * DD + t], v1 = z[r1 * DD + t];
        float v2 = z[r2 * DD + t], v3 = z[r3 * DD + t];
        acc += v0; acc += v1; acc += v2; acc += v3;
    }
    for (; i < hi; i++) acc += z[g_rowlist[i] * DD + t];
    g_epart[blockIdx.x * DD + t] = acc;
}

// -------- combine partials, write e_new / cb_new / n_new --------
__global__ void update_reduce_kernel(const float* __restrict__ n_i,
                                     const float* __restrict__ e_i,
                                     float* __restrict__ out_e, float* __restrict__ out_cb,
                                     float* __restrict__ out_n) {
    int k = blockIdx.x, t = threadIdx.x;
    const float* pp = g_epart + (k * NSEG) * DD + t;
    float acc = 0.f;
    #pragma unroll
    for (int i = 0; i < NSEG; i += 4) {
        float s01 = pp[i * DD] + pp[(i + 1) * DD];
        float s23 = pp[(i + 2) * DD] + pp[(i + 3) * DD];
        acc += s01 + s23;
    }
    const float C1 = (float)(1.0 - 0.99);
    const float NS = (float)(32.0 / (32.0 + 512.0 * 1e-5));
    float nnew = (0.99f * n_i[k] + C1 * (float)g_counts[k] + 1e-5f) * NS;
    float enew = 0.99f * e_i[k * DD + t] + C1 * acc;
    out_e[k * DD + t]  = enew;
    out_cb[k * DD + t] = enew / nnew;
    if (t == 0) out_n[k] = nnew;
}

// -------- gather codes, STE output, commitment-loss partials (linear z) -------
__global__ void gather_kernel(const float* __restrict__ z, const float* __restrict__ cb,
                              float* __restrict__ out_code) {
    float part = 0.f;
    int stride = gridDim.x * blockDim.x;
    for (int idx = blockIdx.x * blockDim.x + threadIdx.x; idx < NV4; idx += stride) {
        float4 zv = ((const float4*)z)[idx];
        int row = idx >> 6;
        int d = (idx & 63) << 2;
        int k = g_enc[row];
        float4 cv = *(const float4*)(cb + k * DD + d);
        float4 o;
        o.x = zv.x + (cv.x - zv.x);
        o.y = zv.y + (cv.y - zv.y);
        o.z = zv.z + (cv.z - zv.z);
        o.w = zv.w + (cv.w - zv.w);
        ((float4*)out_code)[idx] = o;
        float dx = zv.x - cv.x, dy = zv.y - cv.y;
        float dz = zv.z - cv.z, dw = zv.w - cv.w;
        part += dx * dx + dy * dy + dz * dz + dw * dw;
    }
    #pragma unroll
    for (int o = 16; o > 0; o >>= 1) part += __shfl_xor_sync(0xffffffffu, part, o);
    __shared__ float sm[8];
    if ((threadIdx.x & 31) == 0) sm[threadIdx.x >> 5] = part;
    __syncthreads();
    if (threadIdx.x == 0) {
        float tot = 0.f;
        #pragma unroll
        for (int i = 0; i < 8; i++) tot += sm[i];
        g_losspart[blockIdx.x] = (double)tot;
    }
}

__global__ void finalize_kernel(float* __restrict__ out_loss) {
    __shared__ double sm[256];
    double s = 0.0;
    for (int i = threadIdx.x; i < 8192; i += 256) s += g_losspart[i];
    sm[threadIdx.x] = s;
    __syncthreads();
    for (int off = 128; off > 0; off >>= 1) {
        if (threadIdx.x < off) sm[threadIdx.x] += sm[threadIdx.x + off];
        __syncthreads();
    }
    if (threadIdx.x == 0) out_loss[0] = 0.25f * (float)(sm[0] / 33554432.0);
}

extern "C" void kernel_launch(void* const* d_in, const int* in_sizes, int n_in,
                              void* d_out, int out_size) {
    const float* z   = (const float*)d_in[0];
    const float* cb  = (const float*)d_in[1];
    const float* n_i = (const float*)d_in[2];
    const float* e_i = (const float*)d_in[3];
    float* out = (float*)d_out;

    // idempotent attribute set (not a stream op; capture-safe)
    cudaFuncSetAttribute(argmin_tc_kernel,
                         cudaFuncAttributeMaxDynamicSharedMemorySize, SM_TOTAL);

    prep_kernel<<<KK, 256>>>(cb);                                  // #1
    pad_kernel<<<1, 32>>>();                                       // #2
    argmin_tc_kernel<<<NR / 128, 256, SM_TOTAL>>>(z, out + OFF_ENC); // #3 <- ncu
    fixup_kernel<<<128, 256>>>(z, cb, out + OFF_ENC);              // #4 <- ncu
    prefix_kernel<<<1, KK>>>();
    scatter_kernel<<<128, 256>>>();
    update_partial_kernel<<<KK * NSEG, 256>>>(z);
    update_reduce_kernel<<<KK, 256>>>(n_i, e_i, out + OFF_E, out + OFF_CB, out + OFF_N);
    gather_kernel<<<8192, 256>>>(z, cb, out);
    finalize_kernel<<<1, 256>>>(out + OFF_LOSS);
}